// round 14
// baseline (speedup 1.0000x reference)
#include <cuda_runtime.h>
#include <math.h>
#include <stdint.h>

typedef unsigned long long ull;

static const int NN = 100000;
static const int EE = 1600000;

#define EPI_RELU 1
#define EPI_BIAS 2
#define EPI_ADDC 4

// ============================================================================
// cp.async helpers (sm_80+, valid on compute_103)
// ============================================================================
#define CP_ASYNC16(dst_u32, src_ptr) \
    asm volatile("cp.async.cg.shared.global [%0], [%1], 16;" \
                 :: "r"(dst_u32), "l"(src_ptr) : "memory")
#define CP_COMMIT() asm volatile("cp.async.commit_group;" ::: "memory")
#define CP_WAIT0() asm volatile("cp.async.wait_group 0;" ::: "memory")
#define CP_WAIT1() asm volatile("cp.async.wait_group 1;" ::: "memory")

__device__ __forceinline__ uint32_t smem_u32(const void* p) {
    uint32_t a;
    asm("{ .reg .u64 t; cvta.to.shared.u64 t, %1; cvt.u32.u64 %0, t; }"
        : "=r"(a) : "l"(p));
    return a;
}

// bf16 m16n8k16 MMA, fp32 accumulate
#define MMA_BF16(c, a, b) \
    asm volatile( \
        "mma.sync.aligned.m16n8k16.row.col.f32.bf16.bf16.f32 " \
        "{%0,%1,%2,%3}, {%4,%5,%6,%7}, {%8,%9}, {%0,%1,%2,%3};" \
        : "+f"((c)[0]), "+f"((c)[1]), "+f"((c)[2]), "+f"((c)[3]) \
        : "r"((a)[0]), "r"((a)[1]), "r"((a)[2]), "r"((a)[3]), \
          "r"((b)[0]), "r"((b)[1]))

// Split a float2 into packed bf16x2 hi (rounded) and lo (residual, bf16).
__device__ __forceinline__ void split_bf16(float2 v, uint32_t& hi, uint32_t& lo) {
    uint32_t h;
    asm("cvt.rn.bf16x2.f32 %0, %1, %2;" : "=r"(h) : "f"(v.y), "f"(v.x));
    float hx = __uint_as_float(h << 16);
    float hy = __uint_as_float(h & 0xffff0000u);
    float rx = v.x - hx;
    float ry = v.y - hy;
    uint32_t l;
    asm("cvt.rn.bf16x2.f32 %0, %1, %2;" : "=r"(l) : "f"(ry), "f"(rx));
    hi = h;
    lo = l;
}

// Permuted slot within a 16-word (16 k-pair) chunk so that fragment pairs
// (tig, tig+4) of each k16 group are ADJACENT -> one 64-bit LDS.
// j = logical pair index 0..15; slot = (j>>3)*8 + (w<4 ? 2w : 2(w-4)+1), w=j&7.
__device__ __forceinline__ int pair_slot(int j) {
    int w = j & 7;
    return (j & 8) | ((w < 4) ? (2 * w) : (2 * (w - 4) + 1));
}

// ============================================================================
// Scratch (device globals; no allocation allowed)
// ============================================================================
__device__ float g_h1[100000 * 512];
__device__ float g_h2[100000 * 64];
__device__ float g_logits[100000 * 64];
__device__ float g_tp[100000 * 64];
__device__ float g_xh[100000 * 128];
__device__ float g_tmp[100000 * 128];
__device__ float g_a[100000 * 128];
__device__ float g_pv[100000 * 128];
__device__ float g_agg[100000 * 128];
__device__ float g_pos[100000 * 3];
__device__ float g_ew[1600000];
__device__ ull   g_cse[1600000];
__device__ int   g_cnt[100000];
__device__ int   g_off[100001];
__device__ int   g_cur[100000];
__device__ double g_sum2[2];
__device__ float g_ms[2];
__device__ int   g_is64;
// pre-split transposed weights: packed bf16x2 k-pairs, PERMUTED order, [N][K/2]
__device__ uint32_t g_btm1h[512 * 64],  g_btm1l[512 * 64];
__device__ uint32_t g_btm2h[64 * 256],  g_btm2l[64 * 256];
__device__ uint32_t g_btm3h[64 * 32],   g_btm3l[64 * 32];
__device__ uint32_t g_pth[64 * 32],     g_ptl[64 * 32];
__device__ uint32_t g_bti1h[128 * 64],  g_bti1l[128 * 64];
__device__ uint32_t g_bti2h[128 * 64],  g_bti2l[128 * 64];
__device__ uint32_t g_btp1h[128 * 64],  g_btp1l[128 * 64];
__device__ uint32_t g_btlAh[128 * 64],  g_btlAl[128 * 64];
__device__ uint32_t g_btgh[128 * 64],   g_btgl[128 * 64];
__device__ uint32_t g_btfh[64 * 64],    g_btfl[64 * 64];

// ----------------------------------------------------------------------------
// Edge index loader (handles int64 or int32 edge_index)
// ----------------------------------------------------------------------------
__device__ __forceinline__ int load_edge(const void* ei, int which, int e) {
    if (g_is64)
        return (int)reinterpret_cast<const long long*>(ei)[(size_t)which * EE + e];
    return reinterpret_cast<const int*>(ei)[(size_t)which * EE + e];
}

// ----------------------------------------------------------------------------
// Fused prep: transpose + bf16 hi/lo pre-split (permuted order) + parsing +
// edge-dtype detect. 385 blocks x 256 threads; block 384 detects.
// ----------------------------------------------------------------------------
__global__ void prep_kernel(const ull* __restrict__ ei64,
                            const float* __restrict__ Wm1, const float* __restrict__ Wm2,
                            const float* __restrict__ Wm3, const float* __restrict__ P0,
                            const float* __restrict__ Wi1, const float* __restrict__ Wi2,
                            const float* __restrict__ Wp1, const float* __restrict__ Wl,
                            const float* __restrict__ Wg,  const float* __restrict__ Wf) {
    if (blockIdx.x == 384) {
        __shared__ int bad;
        if (threadIdx.x == 0) bad = 0;
        __syncthreads();
        for (int i = threadIdx.x; i < 1024; i += 256)
            if (ei64[i] >= 100000ULL) atomicAdd(&bad, 1);
        __syncthreads();
        if (threadIdx.x == 0) g_is64 = (bad == 0) ? 1 : 0;
        return;
    }
    int i = blockIdx.x * 256 + threadIdx.x;
    const float* W;
    uint32_t *oh, *ol;
    int N, K2, j;
    bool isP = false;
    if (i < 32768)       { W = Wm1; N = 512; K2 = 64;  j = i;          oh = g_btm1h; ol = g_btm1l; }
    else if (i < 49152)  { W = Wm2; N = 64;  K2 = 256; j = i - 32768;  oh = g_btm2h; ol = g_btm2l; }
    else if (i < 51200)  { W = Wm3; N = 64;  K2 = 32;  j = i - 49152;  oh = g_btm3h; ol = g_btm3l; }
    else if (i < 53248)  { W = P0;  N = 64;  K2 = 32;  j = i - 51200;  oh = g_pth;   ol = g_ptl; isP = true; }
    else if (i < 61440)  { W = Wi1; N = 128; K2 = 64;  j = i - 53248;  oh = g_bti1h; ol = g_bti1l; }
    else if (i < 69632)  { W = Wi2; N = 128; K2 = 64;  j = i - 61440;  oh = g_bti2h; ol = g_bti2l; }
    else if (i < 77824)  { W = Wp1; N = 128; K2 = 64;  j = i - 69632;  oh = g_btp1h; ol = g_btp1l; }
    else if (i < 86016)  { W = Wl;  N = 128; K2 = 64;  j = i - 77824;  oh = g_btlAh; ol = g_btlAl; }
    else if (i < 94208)  { W = Wg;  N = 128; K2 = 64;  j = i - 86016;  oh = g_btgh;  ol = g_btgl; }
    else                 { W = Wf;  N = 64;  K2 = 64;  j = i - 94208;  oh = g_btfh;  ol = g_btfl; }
    int n = j / K2, kp = j % K2;
    float v0 = W[(size_t)(2 * kp) * N + n];
    float v1 = W[(size_t)(2 * kp + 1) * N + n];
    if (isP) { v0 = fmaxf(0.f, 2.0f * v0); v1 = fmaxf(0.f, 2.0f * v1); }
    uint32_t hi, lo;
    split_bf16(make_float2(v0, v1), hi, lo);
    int pos = (kp & ~15) | pair_slot(kp & 15);
    oh[(size_t)n * K2 + pos] = hi;
    ol[(size_t)n * K2 + pos] = lo;
}

// ============================================================================
// bf16x3 (fp32-emulating) mma.sync GEMM.
// Block tile 128xNT (NT=128 or 64), 8 warps (2M x 4N), warp 64x(NT/4), BK=32.
// A: LDG fp32 -> split once at STS -> packed bf16 hi/lo smem (2 buf, permuted).
// B: pre-split + pre-permuted packed bf16 via cp.async (3 buf).
// Mainloop: conflict-free 64-bit LDS + MMA only. One __syncthreads per chunk.
// ============================================================================
template <int NT, int EPI>
__global__ void __launch_bounds__(256, 2)
mma_gemm(const float* __restrict__ A,
         const uint32_t* __restrict__ BH, const uint32_t* __restrict__ BL,
         const float* __restrict__ bias, const float* __restrict__ Cadd,
         float* __restrict__ C, int M, int K, int Nld) {
    constexpr int BM = 128, LDW = 40;   // words/row: 16 hi + 16 lo + 8 pad
    constexpr int WN = NT / 4;
    constexpr int MN = WN / 8;
    extern __shared__ uint32_t smw[];
    uint32_t* Ap = smw;                          // [2][BM][LDW]
    uint32_t* Bp = smw + 2 * BM * LDW;           // [3][NT][LDW]
    const uint32_t bp_b = smem_u32(Bp);

    const int tid = threadIdx.x;
    const int lane = tid & 31;
    const int wid = tid >> 5;
    const int warp_m = wid & 1;
    const int warp_n = wid >> 1;
    const int g = lane >> 2;
    const int tig = lane & 3;

    const int rowBase = blockIdx.x * BM;
    const int colBase = blockIdx.y * NT;
    const int Khalf = K >> 1;
    const uint32_t* BH2 = BH + (size_t)colBase * Khalf;
    const uint32_t* BL2 = BL + (size_t)colBase * Khalf;

    float acc[4][MN][4];
#pragma unroll
    for (int i = 0; i < 4; i++)
#pragma unroll
        for (int j = 0; j < MN; j++)
#pragma unroll
            for (int q = 0; q < 4; q++) acc[i][j][q] = 0.f;

    const int nCh = K >> 5;

    // STS slots for this thread's two k-pairs (depends only on cc = tid&7)
    const int cc0 = tid & 7;
    const int slot0 = pair_slot(2 * cc0);
    const int slot1 = pair_slot(2 * cc0 + 1);

    float4 rA[4];
    auto ldgA = [&](int c) {
        const int k0 = c << 5;
#pragma unroll
        for (int i = 0; i < 4; i++) {
            int q = tid + (i << 8);
            int r = q >> 3, cc = q & 7;
            int gr = rowBase + r;
            if (gr >= M) gr = M - 1;
            rA[i] = *reinterpret_cast<const float4*>(A + (size_t)gr * K + k0 + cc * 4);
        }
    };
    auto stsA = [&](int buf) {
#pragma unroll
        for (int i = 0; i < 4; i++) {
            int q = tid + (i << 8);
            int r = q >> 3;
            uint32_t h0, l0, h1, l1;
            split_bf16(make_float2(rA[i].x, rA[i].y), h0, l0);
            split_bf16(make_float2(rA[i].z, rA[i].w), h1, l1);
            uint32_t* row = Ap + (buf * BM + r) * LDW;
            row[slot0] = h0;
            row[slot1] = h1;
            row[16 + slot0] = l0;
            row[16 + slot1] = l1;
        }
    };
    auto cpB = [&](int c, int tb) {
        const int kp0 = c << 4;
#pragma unroll
        for (int i = 0; i < NT / 32; i++) {
            int q = tid + (i << 8);
            int r = q >> 3, seg = q & 7;
            const uint32_t* src = (seg < 4)
                ? BH2 + (size_t)r * Khalf + kp0 + seg * 4
                : BL2 + (size_t)r * Khalf + kp0 + (seg - 4) * 4;
            int soff = (seg < 4) ? seg * 4 : 16 + (seg - 4) * 4;
            uint32_t dst = bp_b + (uint32_t)(((tb * NT + r) * LDW + soff) * 4);
            CP_ASYNC16(dst, src);
        }
        CP_COMMIT();
    };

    // prologue
    ldgA(0);
    cpB(0, 0);
    stsA(0);
    if (nCh > 1) { ldgA(1); cpB(1, 1); }

    int cbuf = 0, lbuf = 2;
    for (int c = 0; c < nCh; c++) {
        if (c == nCh - 1) { CP_WAIT0(); } else { CP_WAIT1(); }
        __syncthreads();
        if (c + 1 < nCh) stsA((c + 1) & 1);
        if (c + 2 < nCh) { ldgA(c + 2); cpB(c + 2, lbuf); }
        const uint32_t* Ab = Ap + (c & 1) * BM * LDW;
        const uint32_t* Bb = Bp + cbuf * NT * LDW;
#pragma unroll
        for (int ko = 0; ko < 2; ko++) {
            const int kb = ko * 8 + 2 * tig;
            uint32_t bhi[MN][2], blo[MN][2];
#pragma unroll
            for (int mn = 0; mn < MN; mn++) {
                const uint32_t* p = Bb + (warp_n * WN + mn * 8 + g) * LDW + kb;
                uint2 vh = *reinterpret_cast<const uint2*>(p);
                uint2 vl = *reinterpret_cast<const uint2*>(p + 16);
                bhi[mn][0] = vh.x; bhi[mn][1] = vh.y;
                blo[mn][0] = vl.x; blo[mn][1] = vl.y;
            }
#pragma unroll
            for (int mm = 0; mm < 4; mm++) {
                const uint32_t* pa = Ab + (warp_m * 64 + mm * 16 + g) * LDW + kb;
                uint2 h0 = *reinterpret_cast<const uint2*>(pa);
                uint2 l0 = *reinterpret_cast<const uint2*>(pa + 16);
                uint2 h8 = *reinterpret_cast<const uint2*>(pa + 8 * LDW);
                uint2 l8 = *reinterpret_cast<const uint2*>(pa + 8 * LDW + 16);
                uint32_t ahi[4] = {h0.x, h8.x, h0.y, h8.y};
                uint32_t alo[4] = {l0.x, l8.x, l0.y, l8.y};
#pragma unroll
                for (int mn = 0; mn < MN; mn++) {
                    MMA_BF16(acc[mm][mn], ahi, bhi[mn]);
                    MMA_BF16(acc[mm][mn], ahi, blo[mn]);
                    MMA_BF16(acc[mm][mn], alo, bhi[mn]);
                }
            }
        }
        cbuf = (cbuf == 2) ? 0 : cbuf + 1;
        lbuf = (lbuf == 2) ? 0 : lbuf + 1;
    }

    // Epilogue
#pragma unroll
    for (int mm = 0; mm < 4; mm++) {
        const int r0 = rowBase + warp_m * 64 + mm * 16 + g;
        const int r1 = r0 + 8;
#pragma unroll
        for (int mn = 0; mn < MN; mn++) {
            const int col = colBase + warp_n * WN + mn * 8 + 2 * tig;
            float2 v0 = make_float2(acc[mm][mn][0], acc[mm][mn][1]);
            float2 v1 = make_float2(acc[mm][mn][2], acc[mm][mn][3]);
            if (EPI & EPI_BIAS) {
                float2 bb = *reinterpret_cast<const float2*>(bias + col);
                v0.x += bb.x; v0.y += bb.y;
                v1.x += bb.x; v1.y += bb.y;
            }
            if (r0 < M) {
                float2 o = v0;
                if (EPI & EPI_ADDC) {
                    float2 cc = *reinterpret_cast<const float2*>(Cadd + (size_t)r0 * Nld + col);
                    o.x += cc.x; o.y += cc.y;
                }
                if (EPI & EPI_RELU) { o.x = fmaxf(o.x, 0.f); o.y = fmaxf(o.y, 0.f); }
                *reinterpret_cast<float2*>(C + (size_t)r0 * Nld + col) = o;
            }
            if (r1 < M) {
                float2 o = v1;
                if (EPI & EPI_ADDC) {
                    float2 cc = *reinterpret_cast<const float2*>(Cadd + (size_t)r1 * Nld + col);
                    o.x += cc.x; o.y += cc.y;
                }
                if (EPI & EPI_RELU) { o.x = fmaxf(o.x, 0.f); o.y = fmaxf(o.y, 0.f); }
                *reinterpret_cast<float2*>(C + (size_t)r1 * Nld + col) = o;
            }
        }
    }
}

// ----------------------------------------------------------------------------
// ew[e] = dot64(logits[src], tp[dst]); 8 lanes per edge, xor-reduce.
// ----------------------------------------------------------------------------
__global__ void ew_kernel(const void* __restrict__ ei, const float* __restrict__ logits,
                          const float* __restrict__ tp, float* __restrict__ ew,
                          double* __restrict__ sum2) {
    const int tid = threadIdx.x;
    const int gid = blockIdx.x * 256 + tid;
    const int eg = gid >> 3;
    const int sl = tid & 7;
    const int lane = tid & 31;
    const int wib = tid >> 5;
    const bool valid = eg < EE;
    float val = 0.f;
    if (valid) {
        int s = load_edge(ei, 0, eg);
        int d = load_edge(ei, 1, eg);
        const float4* lp = reinterpret_cast<const float4*>(logits + (size_t)s * 64);
        const float4* tq = reinterpret_cast<const float4*>(tp + (size_t)d * 64);
        float4 a0 = lp[sl * 2], a1 = lp[sl * 2 + 1];
        float4 b0 = tq[sl * 2], b1 = tq[sl * 2 + 1];
        val = a0.x * b0.x + a0.y * b0.y + a0.z * b0.z + a0.w * b0.w +
              a1.x * b1.x + a1.y * b1.y + a1.z * b1.z + a1.w * b1.w;
    }
    val += __shfl_xor_sync(0xffffffffu, val, 4);
    val += __shfl_xor_sync(0xffffffffu, val, 2);
    val += __shfl_xor_sync(0xffffffffu, val, 1);
    if (valid && sl == 0) ew[eg] = val;
    float c1 = (sl == 0 && valid) ? val : 0.f;
    float c2 = c1 * c1;
    c1 += __shfl_xor_sync(0xffffffffu, c1, 8);
    c2 += __shfl_xor_sync(0xffffffffu, c2, 8);
    c1 += __shfl_xor_sync(0xffffffffu, c1, 16);
    c2 += __shfl_xor_sync(0xffffffffu, c2, 16);
    __shared__ float sv[8], sq[8];
    if (lane == 0) { sv[wib] = c1; sq[wib] = c2; }
    __syncthreads();
    if (tid == 0) {
        double s = 0, q = 0;
#pragma unroll
        for (int i = 0; i < 8; i++) { s += (double)sv[i]; q += (double)sq[i]; }
        atomicAdd(sum2 + 0, s);
        atomicAdd(sum2 + 1, q);
    }
}

__global__ void finalize_kernel(const double* __restrict__ sum2, float* __restrict__ ms) {
    double s = sum2[0], q = sum2[1];
    double Ed = (double)EE;
    double mean = s / Ed;
    double var = (q - s * s / Ed) / (Ed - 1.0);
    ms[0] = (float)mean;
    ms[1] = (float)sqrt(1e-4 / var);
}

// ----------------------------------------------------------------------------
// CSR build
// ----------------------------------------------------------------------------
__global__ void count_kernel(const void* __restrict__ ei, int* __restrict__ cnt) {
    int e = blockIdx.x * blockDim.x + threadIdx.x;
    if (e >= EE) return;
    atomicAdd(&cnt[load_edge(ei, 1, e)], 1);
}

__global__ void scan_kernel(const int* __restrict__ cnt, int* __restrict__ off,
                            int* __restrict__ cur) {
    __shared__ int sh[1024];
    const int T = 1024;
    int tid = threadIdx.x;
    const int CH = (NN + T - 1) / T;
    int b0 = tid * CH;
    int loc = 0;
    for (int i = 0; i < CH; i++) {
        int idx = b0 + i;
        if (idx < NN) loc += cnt[idx];
    }
    sh[tid] = loc;
    __syncthreads();
    for (int o = 1; o < T; o <<= 1) {
        int t = (tid >= o) ? sh[tid - o] : 0;
        __syncthreads();
        sh[tid] += t;
        __syncthreads();
    }
    int excl = sh[tid] - loc;
    int run = excl;
    for (int i = 0; i < CH; i++) {
        int idx = b0 + i;
        if (idx < NN) {
            off[idx] = run;
            cur[idx] = run;
            run += cnt[idx];
        }
    }
    if (tid == T - 1) off[NN] = EE;
}

__global__ void scatter_kernel(const void* __restrict__ ei, const float* __restrict__ ew,
                               int* __restrict__ cur, ull* __restrict__ cse) {
    int e = blockIdx.x * blockDim.x + threadIdx.x;
    if (e >= EE) return;
    int d = load_edge(ei, 1, e);
    int p = atomicAdd(&cur[d], 1);
    ull pack = ((ull)__float_as_uint(ew[e]) << 32) | (uint32_t)load_edge(ei, 0, e);
    cse[p] = pack;
}

// ----------------------------------------------------------------------------
// pos = t2 @ Wp2 + bp2 (K=128, Nout=3). One warp per node.
// ----------------------------------------------------------------------------
__global__ void pos_kernel(const float* __restrict__ t2, const float* __restrict__ Wp2,
                           const float* __restrict__ bp2, float* __restrict__ pos) {
    __shared__ float sw[384];
    for (int i = threadIdx.x; i < 384; i += blockDim.x) sw[i] = Wp2[i];
    __syncthreads();
    int gw = (blockIdx.x * blockDim.x + threadIdx.x) >> 5;
    int lane = threadIdx.x & 31;
    if (gw >= NN) return;
    float4 v = *reinterpret_cast<const float4*>(t2 + (size_t)gw * 128 + lane * 4);
    int k0 = lane * 4;
    float p0 = v.x * sw[k0 * 3 + 0] + v.y * sw[(k0 + 1) * 3 + 0] +
               v.z * sw[(k0 + 2) * 3 + 0] + v.w * sw[(k0 + 3) * 3 + 0];
    float p1 = v.x * sw[k0 * 3 + 1] + v.y * sw[(k0 + 1) * 3 + 1] +
               v.z * sw[(k0 + 2) * 3 + 1] + v.w * sw[(k0 + 3) * 3 + 1];
    float p2 = v.x * sw[k0 * 3 + 2] + v.y * sw[(k0 + 1) * 3 + 2] +
               v.z * sw[(k0 + 2) * 3 + 2] + v.w * sw[(k0 + 3) * 3 + 2];
#pragma unroll
    for (int o = 16; o; o >>= 1) {
        p0 += __shfl_down_sync(0xffffffffu, p0, o);
        p1 += __shfl_down_sync(0xffffffffu, p1, o);
        p2 += __shfl_down_sync(0xffffffffu, p2, o);
    }
    if (lane == 0) {
        pos[gw * 3 + 0] = p0 + __ldg(bp2 + 0);
        pos[gw * 3 + 1] = p1 + __ldg(bp2 + 1);
        pos[gw * 3 + 2] = p2 + __ldg(bp2 + 2);
    }
}

__global__ void pv_kernel(const float* __restrict__ pos, const float* __restrict__ WlB,
                          float* __restrict__ pv) {
    int idx = blockIdx.x * blockDim.x + threadIdx.x;
    if (idx >= NN * 128) return;
    int n = idx >> 7, j = idx & 127;
    float p0 = __ldg(pos + n * 3 + 0);
    float p1 = __ldg(pos + n * 3 + 1);
    float p2 = __ldg(pos + n * 3 + 2);
    pv[idx] = p0 * __ldg(WlB + j) + p1 * __ldg(WlB + 128 + j) + p2 * __ldg(WlB + 256 + j);
}

// ----------------------------------------------------------------------------
// Aggregation: warp per dst node, software-pipelined 4-wide gather.
// ----------------------------------------------------------------------------
__global__ void agg_kernel(const int* __restrict__ off, const ull* __restrict__ cse,
                           const float* __restrict__ ms,
                           const float* __restrict__ a, const float* __restrict__ pv,
                           float* __restrict__ agg) {
    int gw = (blockIdx.x * blockDim.x + threadIdx.x) >> 5;
    int lane = threadIdx.x & 31;
    if (gw >= NN) return;
    const float m = __ldg(ms + 0), sc = __ldg(ms + 1);
    const float c0 = 1.0f - m * sc;
    int beg = __ldg(off + gw), end = __ldg(off + gw + 1);
    const int n = end - beg;
    const float4 pvd = *reinterpret_cast<const float4*>(pv + (size_t)gw * 128 + lane * 4);
    float4 mA = make_float4(-INFINITY, -INFINITY, -INFINITY, -INFINITY);
    float4 mB = mA;
    ull q0 = 0, q1 = 0, q2 = 0, q3 = 0;
    if (n > 0) q0 = __ldg(cse + beg);
    if (n > 1) q1 = __ldg(cse + beg + 1);
    if (n > 2) q2 = __ldg(cse + beg + 2);
    if (n > 3) q3 = __ldg(cse + beg + 3);
    int e = 0;
    while (e + 4 <= n) {
        const int s0 = (int)(uint32_t)q0, s1 = (int)(uint32_t)q1;
        const int s2 = (int)(uint32_t)q2, s3 = (int)(uint32_t)q3;
        const float w0 = fmaf(__uint_as_float((uint32_t)(q0 >> 32)), sc, c0);
        const float w1 = fmaf(__uint_as_float((uint32_t)(q1 >> 32)), sc, c0);
        const float w2 = fmaf(__uint_as_float((uint32_t)(q2 >> 32)), sc, c0);
        const float w3 = fmaf(__uint_as_float((uint32_t)(q3 >> 32)), sc, c0);
        const float4 v0 = *reinterpret_cast<const float4*>(a + (size_t)s0 * 128 + lane * 4);
        const float4 v1 = *reinterpret_cast<const float4*>(a + (size_t)s1 * 128 + lane * 4);
        const float4 v2 = *reinterpret_cast<const float4*>(a + (size_t)s2 * 128 + lane * 4);
        const float4 v3 = *reinterpret_cast<const float4*>(a + (size_t)s3 * 128 + lane * 4);
        const int ne = e + 4;
        if (ne + 0 < n) q0 = __ldg(cse + beg + ne + 0);
        if (ne + 1 < n) q1 = __ldg(cse + beg + ne + 1);
        if (ne + 2 < n) q2 = __ldg(cse + beg + ne + 2);
        if (ne + 3 < n) q3 = __ldg(cse + beg + ne + 3);
        mA.x = fmaxf(mA.x, (v0.x - pvd.x) * w0);
        mA.y = fmaxf(mA.y, (v0.y - pvd.y) * w0);
        mA.z = fmaxf(mA.z, (v0.z - pvd.z) * w0);
        mA.w = fmaxf(mA.w, (v0.w - pvd.w) * w0);
        mB.x = fmaxf(mB.x, (v1.x - pvd.x) * w1);
        mB.y = fmaxf(mB.y, (v1.y - pvd.y) * w1);
        mB.z = fmaxf(mB.z, (v1.z - pvd.z) * w1);
        mB.w = fmaxf(mB.w, (v1.w - pvd.w) * w1);
        mA.x = fmaxf(mA.x, (v2.x - pvd.x) * w2);
        mA.y = fmaxf(mA.y, (v2.y - pvd.y) * w2);
        mA.z = fmaxf(mA.z, (v2.z - pvd.z) * w2);
        mA.w = fmaxf(mA.w, (v2.w - pvd.w) * w2);
        mB.x = fmaxf(mB.x, (v3.x - pvd.x) * w3);
        mB.y = fmaxf(mB.y, (v3.y - pvd.y) * w3);
        mB.z = fmaxf(mB.z, (v3.z - pvd.z) * w3);
        mB.w = fmaxf(mB.w, (v3.w - pvd.w) * w3);
        e = ne;
    }
    const int rem = n - e;
    if (rem > 0) {
        int s0 = (int)(uint32_t)q0;
        float w0 = fmaf(__uint_as_float((uint32_t)(q0 >> 32)), sc, c0);
        const float4 v0 = *reinterpret_cast<const float4*>(a + (size_t)s0 * 128 + lane * 4);
        mA.x = fmaxf(mA.x, (v0.x - pvd.x) * w0);
        mA.y = fmaxf(mA.y, (v0.y - pvd.y) * w0);
        mA.z = fmaxf(mA.z, (v0.z - pvd.z) * w0);
        mA.w = fmaxf(mA.w, (v0.w - pvd.w) * w0);
    }
    if (rem > 1) {
        int s1 = (int)(uint32_t)q1;
        float w1 = fmaf(__uint_as_float((uint32_t)(q1 >> 32)), sc, c0);
        const float4 v1 = *reinterpret_cast<const float4*>(a + (size_t)s1 * 128 + lane * 4);
        mB.x = fmaxf(mB.x, (v1.x - pvd.x) * w1);
        mB.y = fmaxf(mB.y, (v1.y - pvd.y) * w1);
        mB.z = fmaxf(mB.z, (v1.z - pvd.z) * w1);
        mB.w = fmaxf(mB.w, (v1.w - pvd.w) * w1);
    }
    if (rem > 2) {
        int s2 = (int)(uint32_t)q2;
        float w2 = fmaf(__uint_as_float((uint32_t)(q2 >> 32)), sc, c0);
        const float4 v2 = *reinterpret_cast<const float4*>(a + (size_t)s2 * 128 + lane * 4);
        mA.x = fmaxf(mA.x, (v2.x - pvd.x) * w2);
        mA.y = fmaxf(mA.y, (v2.y - pvd.y) * w2);
        mA.z = fmaxf(mA.z, (v2.z - pvd.z) * w2);
        mA.w = fmaxf(mA.w, (v2.w - pvd.w) * w2);
    }
    float4 r;
    if (n == 0) {
        r = make_float4(0.f, 0.f, 0.f, 0.f);
    } else {
        r = make_float4(fmaxf(mA.x, mB.x), fmaxf(mA.y, mB.y),
                        fmaxf(mA.z, mB.z), fmaxf(mA.w, mB.w));
    }
    *reinterpret_cast<float4*>(agg + (size_t)gw * 128 + lane * 4) = r;
}

// ----------------------------------------------------------------------------
// Host launcher
// ----------------------------------------------------------------------------
extern "C" void kernel_launch(void* const* d_in, const int* in_sizes, int n_in,
                              void* d_out, int out_size) {
    const float* x   = (const float*)d_in[0];
    const void*  ei  = d_in[1];
    const float* Wm1 = (const float*)d_in[2];  const float* bm1 = (const float*)d_in[3];
    const float* Wm2 = (const float*)d_in[4];  const float* bm2 = (const float*)d_in[5];
    const float* Wm3 = (const float*)d_in[6];  const float* bm3 = (const float*)d_in[7];
    const float* P0  = (const float*)d_in[8];
    const float* Wi1 = (const float*)d_in[9];  const float* bi1 = (const float*)d_in[10];
    const float* Wi2 = (const float*)d_in[11]; const float* bi2 = (const float*)d_in[12];
    const float* Wp1 = (const float*)d_in[13]; const float* bp1 = (const float*)d_in[14];
    const float* Wp2 = (const float*)d_in[15]; const float* bp2 = (const float*)d_in[16];
    const float* Wl  = (const float*)d_in[17]; const float* bl  = (const float*)d_in[18];
    const float* Wg  = (const float*)d_in[19]; const float* bg  = (const float*)d_in[20];
    const float* Wf  = (const float*)d_in[21]; const float* bf  = (const float*)d_in[22];
    float* out = (float*)d_out;

    float *h1, *h2, *logits, *tp, *xh, *tmp, *a, *pv, *agg, *pos, *ew, *ms;
    uint32_t *btm1h, *btm1l, *btm2h, *btm2l, *btm3h, *btm3l, *pth, *ptl;
    uint32_t *bti1h, *bti1l, *bti2h, *bti2l, *btp1h, *btp1l;
    uint32_t *btlAh, *btlAl, *btgh, *btgl, *btfh, *btfl;
    int *cnt, *off, *cur;
    ull* cse;
    double* sum2;
    cudaGetSymbolAddress((void**)&h1, g_h1);
    cudaGetSymbolAddress((void**)&h2, g_h2);
    cudaGetSymbolAddress((void**)&logits, g_logits);
    cudaGetSymbolAddress((void**)&tp, g_tp);
    cudaGetSymbolAddress((void**)&xh, g_xh);
    cudaGetSymbolAddress((void**)&tmp, g_tmp);
    cudaGetSymbolAddress((void**)&a, g_a);
    cudaGetSymbolAddress((void**)&pv, g_pv);
    cudaGetSymbolAddress((void**)&agg, g_agg);
    cudaGetSymbolAddress((void**)&pos, g_pos);
    cudaGetSymbolAddress((void**)&ew, g_ew);
    cudaGetSymbolAddress((void**)&ms, g_ms);
    cudaGetSymbolAddress((void**)&cnt, g_cnt);
    cudaGetSymbolAddress((void**)&off, g_off);
    cudaGetSymbolAddress((void**)&cur, g_cur);
    cudaGetSymbolAddress((void**)&cse, g_cse);
    cudaGetSymbolAddress((void**)&sum2, g_sum2);
    cudaGetSymbolAddress((void**)&btm1h, g_btm1h); cudaGetSymbolAddress((void**)&btm1l, g_btm1l);
    cudaGetSymbolAddress((void**)&btm2h, g_btm2h); cudaGetSymbolAddress((void**)&btm2l, g_btm2l);
    cudaGetSymbolAddress((void**)&btm3h, g_btm3h); cudaGetSymbolAddress((void**)&btm3l, g_btm3l);
    cudaGetSymbolAddress((void**)&pth, g_pth);     cudaGetSymbolAddress((void**)&ptl, g_ptl);
    cudaGetSymbolAddress((void**)&bti1h, g_bti1h); cudaGetSymbolAddress((void**)&bti1l, g_bti1l);
    cudaGetSymbolAddress((void**)&bti2h, g_bti2h); cudaGetSymbolAddress((void**)&bti2l, g_bti2l);
    cudaGetSymbolAddress((void**)&btp1h, g_btp1h); cudaGetSymbolAddress((void**)&btp1l, g_btp1l);
    cudaGetSymbolAddress((void**)&btlAh, g_btlAh); cudaGetSymbolAddress((void**)&btlAl, g_btlAl);
    cudaGetSymbolAddress((void**)&btgh, g_btgh);   cudaGetSymbolAddress((void**)&btgl, g_btgl);
    cudaGetSymbolAddress((void**)&btfh, g_btfh);   cudaGetSymbolAddress((void**)&btfl, g_btfl);

    const int GM = (NN + 127) / 128;  // 782
    const int SM128 = (2 * 128 * 40 + 3 * 128 * 40) * 4;  // 102400
    const int SM64  = (2 * 128 * 40 + 3 * 64 * 40) * 4;   // 71680

    cudaFuncSetAttribute(mma_gemm<128, EPI_BIAS | EPI_RELU>,
                         cudaFuncAttributeMaxDynamicSharedMemorySize, SM128);
    cudaFuncSetAttribute(mma_gemm<128, EPI_BIAS>,
                         cudaFuncAttributeMaxDynamicSharedMemorySize, SM128);
    cudaFuncSetAttribute(mma_gemm<128, EPI_BIAS | EPI_ADDC>,
                         cudaFuncAttributeMaxDynamicSharedMemorySize, SM128);
    cudaFuncSetAttribute(mma_gemm<64, EPI_BIAS | EPI_RELU>,
                         cudaFuncAttributeMaxDynamicSharedMemorySize, SM64);
    cudaFuncSetAttribute(mma_gemm<64, EPI_BIAS>,
                         cudaFuncAttributeMaxDynamicSharedMemorySize, SM64);
    cudaFuncSetAttribute(mma_gemm<64, 0>,
                         cudaFuncAttributeMaxDynamicSharedMemorySize, SM64);

    // fused prep (transpose + bf16 pre-split permuted + parsing + dtype detect)
    prep_kernel<<<385, 256>>>((const ull*)ei, Wm1, Wm2, Wm3, P0, Wi1, Wi2, Wp1, Wl, Wg, Wf);
    cudaMemsetAsync(cnt, 0, NN * sizeof(int));
    cudaMemsetAsync(sum2, 0, 2 * sizeof(double));

    // CSR counts (needs is64 from prep)
    count_kernel<<<6250, 256>>>(ei, cnt);
    scan_kernel<<<1, 1024>>>(cnt, off, cur);

    // pseudo-MLP chain
    mma_gemm<128, EPI_BIAS | EPI_RELU><<<dim3(GM, 4), 256, SM128>>>(x, btm1h, btm1l, bm1, nullptr, h1, NN, 128, 512);
    mma_gemm<64, EPI_BIAS | EPI_RELU><<<dim3(GM, 1), 256, SM64>>>(h1, btm2h, btm2l, bm2, nullptr, h2, NN, 512, 64);
    mma_gemm<64, EPI_BIAS><<<dim3(GM, 1), 256, SM64>>>(h2, btm3h, btm3l, bm3, nullptr, logits, NN, 64, 64);
    mma_gemm<64, 0><<<dim3(GM, 1), 256, SM64>>>(logits, pth, ptl, nullptr, nullptr, tp, NN, 64, 64);

    // edge weights + CSR scatter (fused permute into packed src|w)
    ew_kernel<<<50000, 256>>>(ei, logits, tp, ew, sum2);
    finalize_kernel<<<1, 1>>>(sum2, ms);
    scatter_kernel<<<6250, 256>>>(ei, ew, cur, cse);

    // initial MLP
    mma_gemm<128, EPI_BIAS | EPI_RELU><<<dim3(GM, 1), 256, SM128>>>(x, bti1h, bti1l, bi1, nullptr, tmp, NN, 128, 128);
    mma_gemm<128, EPI_BIAS><<<dim3(GM, 1), 256, SM128>>>(tmp, bti2h, bti2l, bi2, nullptr, xh, NN, 128, 128);

    // pos / pv
    mma_gemm<128, EPI_BIAS | EPI_RELU><<<dim3(GM, 1), 256, SM128>>>(xh, btp1h, btp1l, bp1, nullptr, tmp, NN, 128, 128);
    pos_kernel<<<12500, 256>>>(tmp, Wp2, bp2, pos);
    pv_kernel<<<50000, 256>>>(pos, Wl + 128 * 128, pv);

    // 2 PointNetConv layers (shared weights)
    for (int layer = 0; layer < 2; layer++) {
        mma_gemm<128, EPI_BIAS | EPI_ADDC><<<dim3(GM, 1), 256, SM128>>>(xh, btlAh, btlAl, bl, pv, a, NN, 128, 128);
        agg_kernel<<<12500, 256>>>(off, cse, ms, a, pv, agg);
        mma_gemm<128, EPI_BIAS | EPI_RELU><<<dim3(GM, 1), 256, SM128>>>(agg, btgh, btgl, bg, nullptr, xh, NN, 128, 128);
    }

    // out = xh @ Wf + bf
    mma_gemm<64, EPI_BIAS><<<dim3(GM, 1), 256, SM64>>>(xh, btfh, btfl, bf, nullptr, out, NN, 128, 64);
}

// round 16
// speedup vs baseline: 1.2544x; 1.2544x over previous
#include <cuda_runtime.h>
#include <math.h>
#include <stdint.h>

typedef unsigned long long ull;

static const int NN = 100000;
static const int EE = 1600000;

#define EPI_RELU 1
#define EPI_BIAS 2
#define EPI_ADDC 4

// ============================================================================
// cp.async helpers (sm_80+, valid on compute_103)
// ============================================================================
#define CP_ASYNC16(dst_u32, src_ptr) \
    asm volatile("cp.async.cg.shared.global [%0], [%1], 16;" \
                 :: "r"(dst_u32), "l"(src_ptr) : "memory")
#define CP_COMMIT() asm volatile("cp.async.commit_group;" ::: "memory")
#define CP_WAIT0() asm volatile("cp.async.wait_group 0;" ::: "memory")
#define CP_WAIT1() asm volatile("cp.async.wait_group 1;" ::: "memory")

__device__ __forceinline__ uint32_t smem_u32(const void* p) {
    uint32_t a;
    asm("{ .reg .u64 t; cvta.to.shared.u64 t, %1; cvt.u32.u64 %0, t; }"
        : "=r"(a) : "l"(p));
    return a;
}

// bf16 m16n8k16 MMA, fp32 accumulate
#define MMA_BF16(c, a, b) \
    asm volatile( \
        "mma.sync.aligned.m16n8k16.row.col.f32.bf16.bf16.f32 " \
        "{%0,%1,%2,%3}, {%4,%5,%6,%7}, {%8,%9}, {%0,%1,%2,%3};" \
        : "+f"((c)[0]), "+f"((c)[1]), "+f"((c)[2]), "+f"((c)[3]) \
        : "r"((a)[0]), "r"((a)[1]), "r"((a)[2]), "r"((a)[3]), \
          "r"((b)[0]), "r"((b)[1]))

// Split a float2 into packed bf16x2 hi (rounded) and lo (residual, bf16).
__device__ __forceinline__ void split_bf16(float2 v, uint32_t& hi, uint32_t& lo) {
    uint32_t h;
    asm("cvt.rn.bf16x2.f32 %0, %1, %2;" : "=r"(h) : "f"(v.y), "f"(v.x));
    float hx = __uint_as_float(h << 16);
    float hy = __uint_as_float(h & 0xffff0000u);
    float rx = v.x - hx;
    float ry = v.y - hy;
    uint32_t l;
    asm("cvt.rn.bf16x2.f32 %0, %1, %2;" : "=r"(l) : "f"(ry), "f"(rx));
    hi = h;
    lo = l;
}

// ============================================================================
// Scratch (device globals; no allocation allowed)
// ============================================================================
__device__ float g_h1[100000 * 512];
__device__ float g_h2[100000 * 64];
__device__ float g_logits[100000 * 64];
__device__ float g_tp[100000 * 64];
__device__ float g_xh[100000 * 128];
__device__ float g_tmp[100000 * 128];
__device__ float g_a[100000 * 128];
__device__ float g_pv[100000 * 128];
__device__ float g_agg[100000 * 128];
__device__ float g_pos[100000 * 3];
__device__ float g_ew[1600000];
__device__ ull   g_cse[1600000];     // packed (w_bits<<32)|src per CSR slot
__device__ int   g_cnt[100000];
__device__ int   g_off[100001];
__device__ int   g_cur[100000];
__device__ double g_sum2[2];
__device__ float g_ms[2];
__device__ int   g_is64;
// pre-split transposed weights: packed bf16x2 k-pairs, [N][K/2] uint32
__device__ uint32_t g_btm1h[512 * 64],  g_btm1l[512 * 64];
__device__ uint32_t g_btm2h[64 * 256],  g_btm2l[64 * 256];
__device__ uint32_t g_btm3h[64 * 32],   g_btm3l[64 * 32];
__device__ uint32_t g_pth[64 * 32],     g_ptl[64 * 32];
__device__ uint32_t g_bti1h[128 * 64],  g_bti1l[128 * 64];
__device__ uint32_t g_bti2h[128 * 64],  g_bti2l[128 * 64];
__device__ uint32_t g_btp1h[128 * 64],  g_btp1l[128 * 64];
__device__ uint32_t g_btlAh[128 * 64],  g_btlAl[128 * 64];
__device__ uint32_t g_btgh[128 * 64],   g_btgl[128 * 64];
__device__ uint32_t g_btfh[64 * 64],    g_btfl[64 * 64];

// ----------------------------------------------------------------------------
// Edge index loader (handles int64 or int32 edge_index)
// ----------------------------------------------------------------------------
__device__ __forceinline__ int load_edge(const void* ei, int which, int e) {
    if (g_is64)
        return (int)reinterpret_cast<const long long*>(ei)[(size_t)which * EE + e];
    return reinterpret_cast<const int*>(ei)[(size_t)which * EE + e];
}

// ----------------------------------------------------------------------------
// Fused prep: transpose + bf16 hi/lo pre-split of all weights + parsing +
// edge-dtype detect. 385 blocks x 256 threads; block 384 detects.
// ----------------------------------------------------------------------------
__global__ void prep_kernel(const ull* __restrict__ ei64,
                            const float* __restrict__ Wm1, const float* __restrict__ Wm2,
                            const float* __restrict__ Wm3, const float* __restrict__ P0,
                            const float* __restrict__ Wi1, const float* __restrict__ Wi2,
                            const float* __restrict__ Wp1, const float* __restrict__ Wl,
                            const float* __restrict__ Wg,  const float* __restrict__ Wf) {
    if (blockIdx.x == 384) {
        __shared__ int bad;
        if (threadIdx.x == 0) bad = 0;
        __syncthreads();
        for (int i = threadIdx.x; i < 1024; i += 256)
            if (ei64[i] >= 100000ULL) atomicAdd(&bad, 1);
        __syncthreads();
        if (threadIdx.x == 0) g_is64 = (bad == 0) ? 1 : 0;
        return;
    }
    int i = blockIdx.x * 256 + threadIdx.x;
    const float* W;
    uint32_t *oh, *ol;
    int N, K2, j;
    bool isP = false;
    if (i < 32768)       { W = Wm1; N = 512; K2 = 64;  j = i;          oh = g_btm1h; ol = g_btm1l; }
    else if (i < 49152)  { W = Wm2; N = 64;  K2 = 256; j = i - 32768;  oh = g_btm2h; ol = g_btm2l; }
    else if (i < 51200)  { W = Wm3; N = 64;  K2 = 32;  j = i - 49152;  oh = g_btm3h; ol = g_btm3l; }
    else if (i < 53248)  { W = P0;  N = 64;  K2 = 32;  j = i - 51200;  oh = g_pth;   ol = g_ptl; isP = true; }
    else if (i < 61440)  { W = Wi1; N = 128; K2 = 64;  j = i - 53248;  oh = g_bti1h; ol = g_bti1l; }
    else if (i < 69632)  { W = Wi2; N = 128; K2 = 64;  j = i - 61440;  oh = g_bti2h; ol = g_bti2l; }
    else if (i < 77824)  { W = Wp1; N = 128; K2 = 64;  j = i - 69632;  oh = g_btp1h; ol = g_btp1l; }
    else if (i < 86016)  { W = Wl;  N = 128; K2 = 64;  j = i - 77824;  oh = g_btlAh; ol = g_btlAl; }
    else if (i < 94208)  { W = Wg;  N = 128; K2 = 64;  j = i - 86016;  oh = g_btgh;  ol = g_btgl; }
    else                 { W = Wf;  N = 64;  K2 = 64;  j = i - 94208;  oh = g_btfh;  ol = g_btfl; }
    int n = j / K2, kp = j % K2;
    float v0 = W[(size_t)(2 * kp) * N + n];
    float v1 = W[(size_t)(2 * kp + 1) * N + n];
    if (isP) { v0 = fmaxf(0.f, 2.0f * v0); v1 = fmaxf(0.f, 2.0f * v1); }
    uint32_t hi, lo;
    split_bf16(make_float2(v0, v1), hi, lo);
    oh[(size_t)n * K2 + kp] = hi;
    ol[(size_t)n * K2 + kp] = lo;
}

// ============================================================================
// bf16x3 (fp32-emulating) mma.sync GEMM — exact Round-11 version (proven best).
// A fp32 staged via cp.async, split in mainloop; B pre-split packed bf16 hi/lo.
// Tile 128xNT, BK=32, 8 warps (2Mx4N), warp 64x(NT/4).
// ============================================================================
template <int NT, int EPI>
__global__ void __launch_bounds__(256, 2)
mma_gemm(const float* __restrict__ A,
         const uint32_t* __restrict__ BH, const uint32_t* __restrict__ BL,
         const float* __restrict__ bias, const float* __restrict__ Cadd,
         float* __restrict__ C, int M, int K, int Nld) {
    constexpr int BM = 128, LDK = 40, LDB = 36;
    constexpr int WN = NT / 4;
    constexpr int MM = 4;
    constexpr int MN = WN / 8;
    extern __shared__ float sm[];
    float* As = sm;                                        // [2][BM][LDK] fp32
    uint32_t* Bs = (uint32_t*)(sm + 2 * BM * LDK);         // [2][NT][LDB] packed
    const uint32_t as_b = smem_u32(As);
    const uint32_t bs_b = smem_u32(Bs);

    const int tid = threadIdx.x;
    const int lane = tid & 31;
    const int wid = tid >> 5;
    const int warp_m = wid & 1;
    const int warp_n = wid >> 1;
    const int g = lane >> 2;
    const int tig = lane & 3;

    const int rowBase = blockIdx.x * BM;
    const int colBase = blockIdx.y * NT;
    const int Khalf = K >> 1;
    const uint32_t* BH2 = BH + (size_t)colBase * Khalf;
    const uint32_t* BL2 = BL + (size_t)colBase * Khalf;

    float acc[MM][MN][4];
#pragma unroll
    for (int i = 0; i < MM; i++)
#pragma unroll
        for (int j = 0; j < MN; j++)
#pragma unroll
            for (int q = 0; q < 4; q++) acc[i][j][q] = 0.f;

    const int nCh = K >> 5;

    auto load_stage = [&](int buf, int c) {
        const int k0 = c << 5;
        const int kp0 = c << 4;
#pragma unroll
        for (int i = 0; i < 4; i++) {
            int q = tid + i * 256;
            int r = q >> 3, cc = q & 7;
            int gr = rowBase + r;
            if (gr >= M) gr = M - 1;
            const float* src = A + (size_t)gr * K + k0 + cc * 4;
            uint32_t dst = as_b + (uint32_t)((buf * BM * LDK + r * LDK + cc * 4) * 4);
            CP_ASYNC16(dst, src);
        }
#pragma unroll
        for (int i = 0; i < NT / 32; i++) {
            int q = tid + i * 256;
            int r = q >> 3, seg = q & 7;
            const uint32_t* src = (seg < 4)
                ? BH2 + (size_t)r * Khalf + kp0 + seg * 4
                : BL2 + (size_t)r * Khalf + kp0 + (seg - 4) * 4;
            int soff = (seg < 4) ? seg * 4 : 16 + (seg - 4) * 4;
            uint32_t dst = bs_b + (uint32_t)(((buf * NT + r) * LDB + soff) * 4);
            CP_ASYNC16(dst, src);
        }
        CP_COMMIT();
    };

    load_stage(0, 0);
    if (nCh > 1) load_stage(1, 1);

    for (int c = 0; c < nCh; c++) {
        if (c == nCh - 1) { CP_WAIT0(); } else { CP_WAIT1(); }
        __syncthreads();
        const int buf = c & 1;
        const float* Ab = As + buf * BM * LDK;
        const uint32_t* Bb = Bs + buf * NT * LDB;
#pragma unroll
        for (int ko = 0; ko < 2; ko++) {
            const int k16 = ko * 16;
            uint32_t bhi[MN][2], blo[MN][2];
#pragma unroll
            for (int mn = 0; mn < MN; mn++) {
                const uint32_t* p = Bb + (warp_n * WN + mn * 8 + g) * LDB + ko * 8 + tig;
                bhi[mn][0] = p[0];
                bhi[mn][1] = p[4];
                blo[mn][0] = p[16];
                blo[mn][1] = p[20];
            }
#pragma unroll
            for (int mm = 0; mm < MM; mm++) {
                const float* p = Ab + (warp_m * 64 + mm * 16 + g) * LDK + k16 + 2 * tig;
                float2 u0 = *reinterpret_cast<const float2*>(p);
                float2 u1 = *reinterpret_cast<const float2*>(p + 8 * LDK);
                float2 u2 = *reinterpret_cast<const float2*>(p + 8);
                float2 u3 = *reinterpret_cast<const float2*>(p + 8 * LDK + 8);
                uint32_t ahi[4], alo[4];
                split_bf16(u0, ahi[0], alo[0]);
                split_bf16(u1, ahi[1], alo[1]);
                split_bf16(u2, ahi[2], alo[2]);
                split_bf16(u3, ahi[3], alo[3]);
#pragma unroll
                for (int mn = 0; mn < MN; mn++) {
                    MMA_BF16(acc[mm][mn], ahi, bhi[mn]);
                    MMA_BF16(acc[mm][mn], ahi, blo[mn]);
                    MMA_BF16(acc[mm][mn], alo, bhi[mn]);
                }
            }
        }
        __syncthreads();
        if (c + 2 < nCh) load_stage(buf, c + 2);
    }

#pragma unroll
    for (int mm = 0; mm < MM; mm++) {
        const int r0 = rowBase + warp_m * 64 + mm * 16 + g;
        const int r1 = r0 + 8;
#pragma unroll
        for (int mn = 0; mn < MN; mn++) {
            const int col = colBase + warp_n * WN + mn * 8 + 2 * tig;
            float2 v0 = make_float2(acc[mm][mn][0], acc[mm][mn][1]);
            float2 v1 = make_float2(acc[mm][mn][2], acc[mm][mn][3]);
            if (EPI & EPI_BIAS) {
                float2 bb = *reinterpret_cast<const float2*>(bias + col);
                v0.x += bb.x; v0.y += bb.y;
                v1.x += bb.x; v1.y += bb.y;
            }
            if (r0 < M) {
                float2 o = v0;
                if (EPI & EPI_ADDC) {
                    float2 cc = *reinterpret_cast<const float2*>(Cadd + (size_t)r0 * Nld + col);
                    o.x += cc.x; o.y += cc.y;
                }
                if (EPI & EPI_RELU) { o.x = fmaxf(o.x, 0.f); o.y = fmaxf(o.y, 0.f); }
                *reinterpret_cast<float2*>(C + (size_t)r0 * Nld + col) = o;
            }
            if (r1 < M) {
                float2 o = v1;
                if (EPI & EPI_ADDC) {
                    float2 cc = *reinterpret_cast<const float2*>(Cadd + (size_t)r1 * Nld + col);
                    o.x += cc.x; o.y += cc.y;
                }
                if (EPI & EPI_RELU) { o.x = fmaxf(o.x, 0.f); o.y = fmaxf(o.y, 0.f); }
                *reinterpret_cast<float2*>(C + (size_t)r1 * Nld + col) = o;
            }
        }
    }
}

// ----------------------------------------------------------------------------
// ew[e] = dot64(logits[src], tp[dst]); 8 lanes per edge, xor-reduce.
// ----------------------------------------------------------------------------
__global__ void ew_kernel(const void* __restrict__ ei, const float* __restrict__ logits,
                          const float* __restrict__ tp, float* __restrict__ ew,
                          double* __restrict__ sum2) {
    const int tid = threadIdx.x;
    const int gid = blockIdx.x * 256 + tid;
    const int eg = gid >> 3;
    const int sl = tid & 7;
    const int lane = tid & 31;
    const int wib = tid >> 5;
    const bool valid = eg < EE;
    float val = 0.f;
    if (valid) {
        int s = load_edge(ei, 0, eg);
        int d = load_edge(ei, 1, eg);
        const float4* lp = reinterpret_cast<const float4*>(logits + (size_t)s * 64);
        const float4* tq = reinterpret_cast<const float4*>(tp + (size_t)d * 64);
        float4 a0 = lp[sl * 2], a1 = lp[sl * 2 + 1];
        float4 b0 = tq[sl * 2], b1 = tq[sl * 2 + 1];
        val = a0.x * b0.x + a0.y * b0.y + a0.z * b0.z + a0.w * b0.w +
              a1.x * b1.x + a1.y * b1.y + a1.z * b1.z + a1.w * b1.w;
    }
    val += __shfl_xor_sync(0xffffffffu, val, 4);
    val += __shfl_xor_sync(0xffffffffu, val, 2);
    val += __shfl_xor_sync(0xffffffffu, val, 1);
    if (valid && sl == 0) ew[eg] = val;
    float c1 = (sl == 0 && valid) ? val : 0.f;
    float c2 = c1 * c1;
    c1 += __shfl_xor_sync(0xffffffffu, c1, 8);
    c2 += __shfl_xor_sync(0xffffffffu, c2, 8);
    c1 += __shfl_xor_sync(0xffffffffu, c1, 16);
    c2 += __shfl_xor_sync(0xffffffffu, c2, 16);
    __shared__ float sv[8], sq[8];
    if (lane == 0) { sv[wib] = c1; sq[wib] = c2; }
    __syncthreads();
    if (tid == 0) {
        double s = 0, q = 0;
#pragma unroll
        for (int i = 0; i < 8; i++) { s += (double)sv[i]; q += (double)sq[i]; }
        atomicAdd(sum2 + 0, s);
        atomicAdd(sum2 + 1, q);
    }
}

__global__ void finalize_kernel(const double* __restrict__ sum2, float* __restrict__ ms) {
    double s = sum2[0], q = sum2[1];
    double Ed = (double)EE;
    double mean = s / Ed;
    double var = (q - s * s / Ed) / (Ed - 1.0);
    ms[0] = (float)mean;
    ms[1] = (float)sqrt(1e-4 / var);
}

// ----------------------------------------------------------------------------
// CSR build
// ----------------------------------------------------------------------------
__global__ void count_kernel(const void* __restrict__ ei, int* __restrict__ cnt) {
    int e = blockIdx.x * blockDim.x + threadIdx.x;
    if (e >= EE) return;
    atomicAdd(&cnt[load_edge(ei, 1, e)], 1);
}

__global__ void scan_kernel(const int* __restrict__ cnt, int* __restrict__ off,
                            int* __restrict__ cur) {
    __shared__ int sh[1024];
    const int T = 1024;
    int tid = threadIdx.x;
    const int CH = (NN + T - 1) / T;
    int b0 = tid * CH;
    int loc = 0;
    for (int i = 0; i < CH; i++) {
        int idx = b0 + i;
        if (idx < NN) loc += cnt[idx];
    }
    sh[tid] = loc;
    __syncthreads();
    for (int o = 1; o < T; o <<= 1) {
        int t = (tid >= o) ? sh[tid - o] : 0;
        __syncthreads();
        sh[tid] += t;
        __syncthreads();
    }
    int excl = sh[tid] - loc;
    int run = excl;
    for (int i = 0; i < CH; i++) {
        int idx = b0 + i;
        if (idx < NN) {
            off[idx] = run;
            cur[idx] = run;
            run += cnt[idx];
        }
    }
    if (tid == T - 1) off[NN] = EE;
}

__global__ void scatter_kernel(const void* __restrict__ ei, const float* __restrict__ ew,
                               int* __restrict__ cur, ull* __restrict__ cse) {
    int e = blockIdx.x * blockDim.x + threadIdx.x;
    if (e >= EE) return;
    int d = load_edge(ei, 1, e);
    int p = atomicAdd(&cur[d], 1);
    ull pack = ((ull)__float_as_uint(ew[e]) << 32) | (uint32_t)load_edge(ei, 0, e);
    cse[p] = pack;
}

// ----------------------------------------------------------------------------
// pos = t2 @ Wp2 + bp2 (K=128, Nout=3). One warp per node.
// ----------------------------------------------------------------------------
__global__ void pos_kernel(const float* __restrict__ t2, const float* __restrict__ Wp2,
                           const float* __restrict__ bp2, float* __restrict__ pos) {
    __shared__ float sw[384];
    for (int i = threadIdx.x; i < 384; i += blockDim.x) sw[i] = Wp2[i];
    __syncthreads();
    int gw = (blockIdx.x * blockDim.x + threadIdx.x) >> 5;
    int lane = threadIdx.x & 31;
    if (gw >= NN) return;
    float4 v = *reinterpret_cast<const float4*>(t2 + (size_t)gw * 128 + lane * 4);
    int k0 = lane * 4;
    float p0 = v.x * sw[k0 * 3 + 0] + v.y * sw[(k0 + 1) * 3 + 0] +
               v.z * sw[(k0 + 2) * 3 + 0] + v.w * sw[(k0 + 3) * 3 + 0];
    float p1 = v.x * sw[k0 * 3 + 1] + v.y * sw[(k0 + 1) * 3 + 1] +
               v.z * sw[(k0 + 2) * 3 + 1] + v.w * sw[(k0 + 3) * 3 + 1];
    float p2 = v.x * sw[k0 * 3 + 2] + v.y * sw[(k0 + 1) * 3 + 2] +
               v.z * sw[(k0 + 2) * 3 + 2] + v.w * sw[(k0 + 3) * 3 + 2];
#pragma unroll
    for (int o = 16; o; o >>= 1) {
        p0 += __shfl_down_sync(0xffffffffu, p0, o);
        p1 += __shfl_down_sync(0xffffffffu, p1, o);
        p2 += __shfl_down_sync(0xffffffffu, p2, o);
    }
    if (lane == 0) {
        pos[gw * 3 + 0] = p0 + __ldg(bp2 + 0);
        pos[gw * 3 + 1] = p1 + __ldg(bp2 + 1);
        pos[gw * 3 + 2] = p2 + __ldg(bp2 + 2);
    }
}

__global__ void pv_kernel(const float* __restrict__ pos, const float* __restrict__ WlB,
                          float* __restrict__ pv) {
    int idx = blockIdx.x * blockDim.x + threadIdx.x;
    if (idx >= NN * 128) return;
    int n = idx >> 7, j = idx & 127;
    float p0 = __ldg(pos + n * 3 + 0);
    float p1 = __ldg(pos + n * 3 + 1);
    float p2 = __ldg(pos + n * 3 + 2);
    pv[idx] = p0 * __ldg(WlB + j) + p1 * __ldg(WlB + 128 + j) + p2 * __ldg(WlB + 256 + j);
}

// ----------------------------------------------------------------------------
// Aggregation: warp per dst node, software-pipelined 4-wide gather.
// ----------------------------------------------------------------------------
__global__ void agg_kernel(const int* __restrict__ off, const ull* __restrict__ cse,
                           const float* __restrict__ ms,
                           const float* __restrict__ a, const float* __restrict__ pv,
                           float* __restrict__ agg) {
    int gw = (blockIdx.x * blockDim.x + threadIdx.x) >> 5;
    int lane = threadIdx.x & 31;
    if (gw >= NN) return;
    const float m = __ldg(ms + 0), sc = __ldg(ms + 1);
    const float c0 = 1.0f - m * sc;
    int beg = __ldg(off + gw), end = __ldg(off + gw + 1);
    const int n = end - beg;
    const float4 pvd = *reinterpret_cast<const float4*>(pv + (size_t)gw * 128 + lane * 4);
    float4 mA = make_float4(-INFINITY, -INFINITY, -INFINITY, -INFINITY);
    float4 mB = mA;
    ull q0 = 0, q1 = 0, q2 = 0, q3 = 0;
    if (n > 0) q0 = __ldg(cse + beg);
    if (n > 1) q1 = __ldg(cse + beg + 1);
    if (n > 2) q2 = __ldg(cse + beg + 2);
    if (n > 3) q3 = __ldg(cse + beg + 3);
    int e = 0;
    while (e + 4 <= n) {
        const int s0 = (int)(uint32_t)q0, s1 = (int)(uint32_t)q1;
        const int s2 = (int)(uint32_t)q2, s3 = (int)(uint32_t)q3;
        const float w0 = fmaf(__uint_as_float((uint32_t)(q0 >> 32)), sc, c0);
        const float w1 = fmaf(__uint_as_float((uint32_t)(q1 >> 32)), sc, c0);
        const float w2 = fmaf(__uint_as_float((uint32_t)(q2 >> 32)), sc, c0);
        const float w3 = fmaf(__uint_as_float((uint32_t)(q3 >> 32)), sc, c0);
        const float4 v0 = *reinterpret_cast<const float4*>(a + (size_t)s0 * 128 + lane * 4);
        const float4 v1 = *reinterpret_cast<const float4*>(a + (size_t)s1 * 128 + lane * 4);
        const float4 v2 = *reinterpret_cast<const float4*>(a + (size_t)s2 * 128 + lane * 4);
        const float4 v3 = *reinterpret_cast<const float4*>(a + (size_t)s3 * 128 + lane * 4);
        const int ne = e + 4;
        if (ne + 0 < n) q0 = __ldg(cse + beg + ne + 0);
        if (ne + 1 < n) q1 = __ldg(cse + beg + ne + 1);
        if (ne + 2 < n) q2 = __ldg(cse + beg + ne + 2);
        if (ne + 3 < n) q3 = __ldg(cse + beg + ne + 3);
        mA.x = fmaxf(mA.x, (v0.x - pvd.x) * w0);
        mA.y = fmaxf(mA.y, (v0.y - pvd.y) * w0);
        mA.z = fmaxf(mA.z, (v0.z - pvd.z) * w0);
        mA.w = fmaxf(mA.w, (v0.w - pvd.w) * w0);
        mB.x = fmaxf(mB.x, (v1.x - pvd.x) * w1);
        mB.y = fmaxf(mB.y, (v1.y - pvd.y) * w1);
        mB.z = fmaxf(mB.z, (v1.z - pvd.z) * w1);
        mB.w = fmaxf(mB.w, (v1.w - pvd.w) * w1);
        mA.x = fmaxf(mA.x, (v2.x - pvd.x) * w2);
        mA.y = fmaxf(mA.y, (v2.y - pvd.y) * w2);
        mA.z = fmaxf(mA.z, (v2.z - pvd.z) * w2);
        mA.w = fmaxf(mA.w, (v2.w - pvd.w) * w2);
        mB.x = fmaxf(mB.x, (v3.x - pvd.x) * w3);
        mB.y = fmaxf(mB.y, (v3.y - pvd.y) * w3);
        mB.z = fmaxf(mB.z, (v3.z - pvd.z) * w3);
        mB.w = fmaxf(mB.w, (v3.w - pvd.w) * w3);
        e = ne;
    }
    const int rem = n - e;
    if (rem > 0) {
        int s0 = (int)(uint32_t)q0;
        float w0 = fmaf(__uint_as_float((uint32_t)(q0 >> 32)), sc, c0);
        const float4 v0 = *reinterpret_cast<const float4*>(a + (size_t)s0 * 128 + lane * 4);
        mA.x = fmaxf(mA.x, (v0.x - pvd.x) * w0);
        mA.y = fmaxf(mA.y, (v0.y - pvd.y) * w0);
        mA.z = fmaxf(mA.z, (v0.z - pvd.z) * w0);
        mA.w = fmaxf(mA.w, (v0.w - pvd.w) * w0);
    }
    if (rem > 1) {
        int s1 = (int)(uint32_t)q1;
        float w1 = fmaf(__uint_as_float((uint32_t)(q1 >> 32)), sc, c0);
        const float4 v1 = *reinterpret_cast<const float4*>(a + (size_t)s1 * 128 + lane * 4);
        mB.x = fmaxf(mB.x, (v1.x - pvd.x) * w1);
        mB.y = fmaxf(mB.y, (v1.y - pvd.y) * w1);
        mB.z = fmaxf(mB.z, (v1.z - pvd.z) * w1);
        mB.w = fmaxf(mB.w, (v1.w - pvd.w) * w1);
    }
    if (rem > 2) {
        int s2 = (int)(uint32_t)q2;
        float w2 = fmaf(__uint_as_float((uint32_t)(q2 >> 32)), sc, c0);
        const float4 v2 = *reinterpret_cast<const float4*>(a + (size_t)s2 * 128 + lane * 4);
        mA.x = fmaxf(mA.x, (v2.x - pvd.x) * w2);
        mA.y = fmaxf(mA.y, (v2.y - pvd.y) * w2);
        mA.z = fmaxf(mA.z, (v2.z - pvd.z) * w2);
        mA.w = fmaxf(mA.w, (v2.w - pvd.w) * w2);
    }
    float4 r;
    if (n == 0) {
        r = make_float4(0.f, 0.f, 0.f, 0.f);
    } else {
        r = make_float4(fmaxf(mA.x, mB.x), fmaxf(mA.y, mB.y),
                        fmaxf(mA.z, mB.z), fmaxf(mA.w, mB.w));
    }
    *reinterpret_cast<float4*>(agg + (size_t)gw * 128 + lane * 4) = r;
}

// ----------------------------------------------------------------------------
// Host launcher — fork/join multi-stream schedule with proper teardown
// ----------------------------------------------------------------------------
extern "C" void kernel_launch(void* const* d_in, const int* in_sizes, int n_in,
                              void* d_out, int out_size) {
    const float* x   = (const float*)d_in[0];
    const void*  ei  = d_in[1];
    const float* Wm1 = (const float*)d_in[2];  const float* bm1 = (const float*)d_in[3];
    const float* Wm2 = (const float*)d_in[4];  const float* bm2 = (const float*)d_in[5];
    const float* Wm3 = (const float*)d_in[6];  const float* bm3 = (const float*)d_in[7];
    const float* P0  = (const float*)d_in[8];
    const float* Wi1 = (const float*)d_in[9];  const float* bi1 = (const float*)d_in[10];
    const float* Wi2 = (const float*)d_in[11]; const float* bi2 = (const float*)d_in[12];
    const float* Wp1 = (const float*)d_in[13]; const float* bp1 = (const float*)d_in[14];
    const float* Wp2 = (const float*)d_in[15]; const float* bp2 = (const float*)d_in[16];
    const float* Wl  = (const float*)d_in[17]; const float* bl  = (const float*)d_in[18];
    const float* Wg  = (const float*)d_in[19]; const float* bg  = (const float*)d_in[20];
    const float* Wf  = (const float*)d_in[21]; const float* bf  = (const float*)d_in[22];
    float* out = (float*)d_out;

    float *h1, *h2, *logits, *tp, *xh, *tmp, *a, *pv, *agg, *pos, *ew, *ms;
    uint32_t *btm1h, *btm1l, *btm2h, *btm2l, *btm3h, *btm3l, *pth, *ptl;
    uint32_t *bti1h, *bti1l, *bti2h, *bti2l, *btp1h, *btp1l;
    uint32_t *btlAh, *btlAl, *btgh, *btgl, *btfh, *btfl;
    int *cnt, *off, *cur;
    ull* cse;
    double* sum2;
    cudaGetSymbolAddress((void**)&h1, g_h1);
    cudaGetSymbolAddress((void**)&h2, g_h2);
    cudaGetSymbolAddress((void**)&logits, g_logits);
    cudaGetSymbolAddress((void**)&tp, g_tp);
    cudaGetSymbolAddress((void**)&xh, g_xh);
    cudaGetSymbolAddress((void**)&tmp, g_tmp);
    cudaGetSymbolAddress((void**)&a, g_a);
    cudaGetSymbolAddress((void**)&pv, g_pv);
    cudaGetSymbolAddress((void**)&agg, g_agg);
    cudaGetSymbolAddress((void**)&pos, g_pos);
    cudaGetSymbolAddress((void**)&ew, g_ew);
    cudaGetSymbolAddress((void**)&ms, g_ms);
    cudaGetSymbolAddress((void**)&cnt, g_cnt);
    cudaGetSymbolAddress((void**)&off, g_off);
    cudaGetSymbolAddress((void**)&cur, g_cur);
    cudaGetSymbolAddress((void**)&cse, g_cse);
    cudaGetSymbolAddress((void**)&sum2, g_sum2);
    cudaGetSymbolAddress((void**)&btm1h, g_btm1h); cudaGetSymbolAddress((void**)&btm1l, g_btm1l);
    cudaGetSymbolAddress((void**)&btm2h, g_btm2h); cudaGetSymbolAddress((void**)&btm2l, g_btm2l);
    cudaGetSymbolAddress((void**)&btm3h, g_btm3h); cudaGetSymbolAddress((void**)&btm3l, g_btm3l);
    cudaGetSymbolAddress((void**)&pth, g_pth);     cudaGetSymbolAddress((void**)&ptl, g_ptl);
    cudaGetSymbolAddress((void**)&bti1h, g_bti1h); cudaGetSymbolAddress((void**)&bti1l, g_bti1l);
    cudaGetSymbolAddress((void**)&bti2h, g_bti2h); cudaGetSymbolAddress((void**)&bti2l, g_bti2l);
    cudaGetSymbolAddress((void**)&btp1h, g_btp1h); cudaGetSymbolAddress((void**)&btp1l, g_btp1l);
    cudaGetSymbolAddress((void**)&btlAh, g_btlAh); cudaGetSymbolAddress((void**)&btlAl, g_btlAl);
    cudaGetSymbolAddress((void**)&btgh, g_btgh);   cudaGetSymbolAddress((void**)&btgl, g_btgl);
    cudaGetSymbolAddress((void**)&btfh, g_btfh);   cudaGetSymbolAddress((void**)&btfl, g_btfl);

    const int GM = (NN + 127) / 128;  // 782
    const int SM128 = 2 * 128 * 40 * 4 + 2 * 128 * 36 * 4;  // 77824
    const int SM64  = 2 * 128 * 40 * 4 + 2 * 64 * 36 * 4;   // 59392

    cudaFuncSetAttribute(mma_gemm<128, EPI_BIAS | EPI_RELU>,
                         cudaFuncAttributeMaxDynamicSharedMemorySize, SM128);
    cudaFuncSetAttribute(mma_gemm<128, EPI_BIAS>,
                         cudaFuncAttributeMaxDynamicSharedMemorySize, SM128);
    cudaFuncSetAttribute(mma_gemm<128, EPI_BIAS | EPI_ADDC>,
                         cudaFuncAttributeMaxDynamicSharedMemorySize, SM128);
    cudaFuncSetAttribute(mma_gemm<64, EPI_BIAS | EPI_RELU>,
                         cudaFuncAttributeMaxDynamicSharedMemorySize, SM64);
    cudaFuncSetAttribute(mma_gemm<64, EPI_BIAS>,
                         cudaFuncAttributeMaxDynamicSharedMemorySize, SM64);
    cudaFuncSetAttribute(mma_gemm<64, 0>,
                         cudaFuncAttributeMaxDynamicSharedMemorySize, SM64);

    // Side streams + events (host objects; destroyed at end of this call)
    cudaStream_t s1, s2;
    cudaStreamCreateWithFlags(&s1, cudaStreamNonBlocking);
    cudaStreamCreateWithFlags(&s2, cudaStreamNonBlocking);
    cudaEvent_t evPrep, evCsr, evEdge;
    cudaEventCreateWithFlags(&evPrep, cudaEventDisableTiming);
    cudaEventCreateWithFlags(&evCsr, cudaEventDisableTiming);
    cudaEventCreateWithFlags(&evEdge, cudaEventDisableTiming);

    // s0: prep, then fork
    prep_kernel<<<385, 256>>>((const ull*)ei, Wm1, Wm2, Wm3, P0, Wi1, Wi2, Wp1, Wl, Wg, Wf);
    cudaEventRecord(evPrep, 0);
    cudaStreamWaitEvent(s1, evPrep, 0);
    cudaStreamWaitEvent(s2, evPrep, 0);

    // s1: CSR count + scan
    cudaMemsetAsync(cnt, 0, NN * sizeof(int), s1);
    count_kernel<<<6250, 256, 0, s1>>>(ei, cnt);
    scan_kernel<<<1, 1024, 0, s1>>>(cnt, off, cur);
    cudaEventRecord(evCsr, s1);

    // s2: pseudo-MLP chain -> ew -> finalize -> scatter
    cudaMemsetAsync(sum2, 0, 2 * sizeof(double), s2);
    mma_gemm<128, EPI_BIAS | EPI_RELU><<<dim3(GM, 4), 256, SM128, s2>>>(x, btm1h, btm1l, bm1, nullptr, h1, NN, 128, 512);
    mma_gemm<64, EPI_BIAS | EPI_RELU><<<dim3(GM, 1), 256, SM64, s2>>>(h1, btm2h, btm2l, bm2, nullptr, h2, NN, 512, 64);
    mma_gemm<64, EPI_BIAS><<<dim3(GM, 1), 256, SM64, s2>>>(h2, btm3h, btm3l, bm3, nullptr, logits, NN, 64, 64);
    mma_gemm<64, 0><<<dim3(GM, 1), 256, SM64, s2>>>(logits, pth, ptl, nullptr, nullptr, tp, NN, 64, 64);
    ew_kernel<<<50000, 256, 0, s2>>>(ei, logits, tp, ew, sum2);
    finalize_kernel<<<1, 1, 0, s2>>>(sum2, ms);
    cudaStreamWaitEvent(s2, evCsr, 0);
    scatter_kernel<<<6250, 256, 0, s2>>>(ei, ew, cur, cse);
    cudaEventRecord(evEdge, s2);

    // s0: initial MLP / pos / pv (concurrent with s1, s2)
    mma_gemm<128, EPI_BIAS | EPI_RELU><<<dim3(GM, 1), 256, SM128>>>(x, bti1h, bti1l, bi1, nullptr, tmp, NN, 128, 128);
    mma_gemm<128, EPI_BIAS><<<dim3(GM, 1), 256, SM128>>>(tmp, bti2h, bti2l, bi2, nullptr, xh, NN, 128, 128);
    mma_gemm<128, EPI_BIAS | EPI_RELU><<<dim3(GM, 1), 256, SM128>>>(xh, btp1h, btp1l, bp1, nullptr, tmp, NN, 128, 128);
    pos_kernel<<<12500, 256>>>(tmp, Wp2, bp2, pos);
    pv_kernel<<<50000, 256>>>(pos, Wl + 128 * 128, pv);

    // layer 1 a-GEMM can start before the edge data is ready
    mma_gemm<128, EPI_BIAS | EPI_ADDC><<<dim3(GM, 1), 256, SM128>>>(xh, btlAh, btlAl, bl, pv, a, NN, 128, 128);

    // join: s0 waits for CSR + edge chains
    cudaStreamWaitEvent(0, evCsr, 0);
    cudaStreamWaitEvent(0, evEdge, 0);

    // 2 PointNetConv layers (shared weights)
    agg_kernel<<<12500, 256>>>(off, cse, ms, a, pv, agg);
    mma_gemm<128, EPI_BIAS | EPI_RELU><<<dim3(GM, 1), 256, SM128>>>(agg, btgh, btgl, bg, nullptr, xh, NN, 128, 128);
    mma_gemm<128, EPI_BIAS | EPI_ADDC><<<dim3(GM, 1), 256, SM128>>>(xh, btlAh, btlAl, bl, pv, a, NN, 128, 128);
    agg_kernel<<<12500, 256>>>(off, cse, ms, a, pv, agg);
    mma_gemm<128, EPI_BIAS | EPI_RELU><<<dim3(GM, 1), 256, SM128>>>(agg, btgh, btgl, bg, nullptr, xh, NN, 128, 128);

    // out = xh @ Wf + bf
    mma_gemm<64, EPI_BIAS><<<dim3(GM, 1), 256, SM64>>>(xh, btfh, btfl, bf, nullptr, out, NN, 128, 64);

    // Teardown: forked streams are fully joined into stream 0 above, so their
    // capture segments are closed — destroying handles here frees the driver
    // resources that the harness's leak tracker flagged in round 15.
    cudaStreamDestroy(s1);
    cudaStreamDestroy(s2);
    cudaEventDestroy(evPrep);
    cudaEventDestroy(evCsr);
    cudaEventDestroy(evEdge);
}